// round 7
// baseline (speedup 1.0000x reference)
#include <cuda_runtime.h>

// SortingRegressionModel: out[i] = dot(sort(x[i,0..2]), W) + b
// Streaming kernel: 96 MB read + 32 MB write. HBM-bound.
//
// R5 kernel, resubmission (broker timeout): persistent one-wave grid
// (148 SMs x 8 CTAs) + grid-stride loop, 8 rows per thread per iteration =
// 6 independent float4 loads (MLP=6), 2 float4 stores, __ldcs/__stcs
// streaming policy.

__device__ __forceinline__ float sort3dot(float a, float b, float c,
                                          float w0, float w1, float w2,
                                          float bias)
{
    float mn = fminf(a, b), mx = fmaxf(a, b);
    float lo = fminf(mn, c);
    float hi = fmaxf(mx, c);
    float mid = fmaxf(mn, fminf(mx, c));
    return fmaf(lo, w0, fmaf(mid, w1, fmaf(hi, w2, bias)));
}

__global__ void __launch_bounds__(256) sort3_linear_persist_kernel(
    const float4* __restrict__ x4,   // x viewed as float4[], 6 per chunk
    const float*  __restrict__ Wp,   // 3 weights
    const float*  __restrict__ bp,   // 1 bias
    float4*       __restrict__ out4, // output viewed as float4[], 2 per chunk
    int n_chunks)                    // number of 8-row chunks (= B/8)
{
    const float w0 = __ldg(Wp + 0);
    const float w1 = __ldg(Wp + 1);
    const float w2 = __ldg(Wp + 2);
    const float bias = __ldg(bp);

    const int stride = gridDim.x * blockDim.x;

    for (int t = blockIdx.x * blockDim.x + threadIdx.x; t < n_chunks;
         t += stride)
    {
        // 6 independent 128-bit streaming loads (front-batched, MLP=6).
        const float4* src = x4 + 6 * (size_t)t;
        const float4 v0 = __ldcs(src + 0);
        const float4 v1 = __ldcs(src + 1);
        const float4 v2 = __ldcs(src + 2);
        const float4 v3 = __ldcs(src + 3);
        const float4 v4 = __ldcs(src + 4);
        const float4 v5 = __ldcs(src + 5);

        float4 o0, o1;
        // rows 0..3 from v0,v1,v2
        o0.x = sort3dot(v0.x, v0.y, v0.z, w0, w1, w2, bias);
        o0.y = sort3dot(v0.w, v1.x, v1.y, w0, w1, w2, bias);
        o0.z = sort3dot(v1.z, v1.w, v2.x, w0, w1, w2, bias);
        o0.w = sort3dot(v2.y, v2.z, v2.w, w0, w1, w2, bias);
        // rows 4..7 from v3,v4,v5
        o1.x = sort3dot(v3.x, v3.y, v3.z, w0, w1, w2, bias);
        o1.y = sort3dot(v3.w, v4.x, v4.y, w0, w1, w2, bias);
        o1.z = sort3dot(v4.z, v4.w, v5.x, w0, w1, w2, bias);
        o1.w = sort3dot(v5.y, v5.z, v5.w, w0, w1, w2, bias);

        __stcs(out4 + 2 * (size_t)t + 0, o0);
        __stcs(out4 + 2 * (size_t)t + 1, o1);
    }
}

// Tail kernel for rows not covered by the vectorized path (B % 8 != 0).
__global__ void sort3_linear_tail_kernel(
    const float* __restrict__ x,
    const float* __restrict__ Wp,
    const float* __restrict__ bp,
    float*       __restrict__ out,
    int start_row, int n_rows)
{
    int i = start_row + blockIdx.x * blockDim.x + threadIdx.x;
    if (i >= n_rows) return;
    float a = x[3 * i + 0], b = x[3 * i + 1], c = x[3 * i + 2];
    out[i] = sort3dot(a, b, c, __ldg(Wp + 0), __ldg(Wp + 1), __ldg(Wp + 2),
                      __ldg(bp));
}

extern "C" void kernel_launch(void* const* d_in, const int* in_sizes, int n_in,
                              void* d_out, int out_size)
{
    const float* x = (const float*)d_in[0];   // [B, 3]
    const float* W = (const float*)d_in[1];   // [1, 3]
    const float* b = (const float*)d_in[2];   // [1]
    float* out = (float*)d_out;               // [B, 1]

    const int B = in_sizes[0] / 3;
    const int n_chunks = B / 8;          // 8 rows per thread-iteration
    const int tail_start = n_chunks * 8;

    if (n_chunks > 0) {
        const int threads = 256;
        // One full wave: 148 SMs (GB300: 152, use 148 floor) x 8 CTAs/SM.
        int blocks = 148 * 8;
        const int max_blocks = (n_chunks + threads - 1) / threads;
        if (blocks > max_blocks) blocks = max_blocks;
        sort3_linear_persist_kernel<<<blocks, threads>>>(
            (const float4*)x, W, b, (float4*)out, n_chunks);
    }
    if (tail_start < B) {
        const int n_tail = B - tail_start;
        sort3_linear_tail_kernel<<<(n_tail + 255) / 256, 256>>>(
            x, W, b, out, tail_start, B);
    }
}